// round 16
// baseline (speedup 1.0000x reference)
#include <cuda_runtime.h>
#include <cstdint>
#include <cstddef>

#define A_DIM 64
#define B_DIM 256
#define D_DIM 128
#define H_DIM 512
#define G4    2048
#define NCTA  128
#define TPB   256
#define NCOLS 256

// ---------------- device scratch (static: no allocations allowed) ----------------
__device__ float g_pre_enc[A_DIM * G4];                       // transposed gate layout
__device__ float g_pre_dec[(size_t)NCOLS * A_DIM * G4];       // transposed gate layout
// h exchange: [parity][replica][cta] -> private 128B line, words 0..3 = h[4*cta .. 4*cta+3]
__device__ __align__(128) float g_hp[2][4][NCTA][32];
// arrival flags: 4 replicas x 128 CTA words (each replica = 4 cache lines)
__device__ __align__(128) unsigned int g_flagU[4][NCTA];
__device__ float g_outs[NCOLS * D_DIM];                       // per-column projections

// new gate column ng = cta*16 + wid*4 + gate  ->  old row = gate*512 + cta*4 + wid
__host__ __device__ __forceinline__ int inv_gate_map(int ng)
{
    const int gate = ng & 3;
    const int w    = (ng >> 2) & 3;
    const int cta  = ng >> 4;
    return gate * H_DIM + cta * 4 + w;
}

// ---------------- pre-activation GEMM (writes transposed gate layout) ----------------
#define BM 64
#define BN 64
#define BK 64

__global__ void pre_gemm_kernel(const float* __restrict__ x,
                                const float* __restrict__ Wih,
                                const float* __restrict__ bih,
                                const float* __restrict__ bhh,
                                int dec)
{
    __shared__ float Xs[BM][BK + 1];
    __shared__ float Ws[BN][BK + 1];
    float* __restrict__ outp = dec ? g_pre_dec : g_pre_enc;

    const int m0 = blockIdx.x * BM;
    const int n0 = blockIdx.y * BN;
    const int tid = threadIdx.x;
    const int tx = tid & 15;
    const int ty = tid >> 4;

    float acc[4][4];
#pragma unroll
    for (int r = 0; r < 4; r++)
#pragma unroll
        for (int c = 0; c < 4; c++) acc[r][c] = 0.f;

    const int lr = tid >> 2;
    const int lc = (tid & 3) * 16;

#pragma unroll
    for (int kit = 0; kit < 2; kit++) {
        const int k0 = kit * BK;
        {
            const int m = m0 + lr;
            const float* src;
            if (dec) {
                const int i = m >> 6;
                const int t = m & 63;
                src = x + ((size_t)(t * B_DIM + (B_DIM - 1 - i))) * D_DIM + k0 + lc;
            } else {
                src = x + ((size_t)(m * B_DIM + (B_DIM - 1))) * D_DIM + k0 + lc;
            }
#pragma unroll
            for (int q = 0; q < 4; q++) {
                float4 v = *(const float4*)(src + q * 4);
                Xs[lr][lc + q * 4 + 0] = v.x;
                Xs[lr][lc + q * 4 + 1] = v.y;
                Xs[lr][lc + q * 4 + 2] = v.z;
                Xs[lr][lc + q * 4 + 3] = v.w;
            }
        }
        {
            const int og = inv_gate_map(n0 + lr);
            const float* src = Wih + (size_t)og * D_DIM + k0 + lc;
#pragma unroll
            for (int q = 0; q < 4; q++) {
                float4 v = *(const float4*)(src + q * 4);
                Ws[lr][lc + q * 4 + 0] = v.x;
                Ws[lr][lc + q * 4 + 1] = v.y;
                Ws[lr][lc + q * 4 + 2] = v.z;
                Ws[lr][lc + q * 4 + 3] = v.w;
            }
        }
        __syncthreads();
#pragma unroll 16
        for (int kk = 0; kk < BK; kk++) {
            float a[4], bb[4];
#pragma unroll
            for (int r = 0; r < 4; r++) a[r] = Xs[ty * 4 + r][kk];
#pragma unroll
            for (int c = 0; c < 4; c++) bb[c] = Ws[tx * 4 + c][kk];
#pragma unroll
            for (int r = 0; r < 4; r++)
#pragma unroll
                for (int c = 0; c < 4; c++) acc[r][c] = fmaf(a[r], bb[c], acc[r][c]);
        }
        __syncthreads();
    }
#pragma unroll
    for (int r = 0; r < 4; r++) {
        const int m = m0 + ty * 4 + r;
#pragma unroll
        for (int c = 0; c < 4; c++) {
            const int ng = n0 + tx * 4 + c;
            const int og = inv_gate_map(ng);
            outp[(size_t)m * G4 + ng] = acc[r][c] + bih[og] + bhh[og];
        }
    }
}

// ---------------- init (runs every launch) ----------------
__global__ void init_kernel()
{
    const int t = blockIdx.x * blockDim.x + threadIdx.x;
    if (t < 2 * 4 * NCTA * 32) ((float*)g_hp)[t] = 0.f;
    if (t < 4 * NCTA) ((unsigned int*)g_flagU)[t] = 0u;
}

// ---------------- fast math helpers ----------------
__device__ __forceinline__ float tanh_fast(float x)
{
    float y;
    asm("tanh.approx.f32 %0, %1;" : "=f"(y) : "f"(x));
    return y;
}
__device__ __forceinline__ float sigm(float x)
{
    return fmaf(tanh_fast(0.5f * x), 0.5f, 0.5f);
}
__device__ __forceinline__ unsigned long long fma2(unsigned long long a,
                                                   unsigned long long b,
                                                   unsigned long long c)
{
    unsigned long long d;
    asm("fma.rn.f32x2 %0, %1, %2, %3;" : "=l"(d) : "l"(a), "l"(b), "l"(c));
    return d;
}
__device__ __forceinline__ unsigned long long add2(unsigned long long a,
                                                   unsigned long long b)
{
    unsigned long long d;
    asm("add.rn.f32x2 %0, %1, %2;" : "=l"(d) : "l"(a), "l"(b));
    return d;
}
__device__ __forceinline__ unsigned long long pack2(float lo, float hi)
{
    return ((unsigned long long)__float_as_uint(hi) << 32) | (unsigned long long)__float_as_uint(lo);
}
__device__ __forceinline__ const float* pre_row(unsigned u)
{
    return (u < A_DIM) ? (g_pre_enc + (size_t)u * G4)
                       : (g_pre_dec + (size_t)(u - A_DIM) * G4);
}

// ---------------- sequential recurrent kernel ----------------
__global__ void __launch_bounds__(TPB, 1) lstm_seq_kernel(
    const float* __restrict__ enc_Whh,
    const float* __restrict__ dec_Whh,
    const float* __restrict__ lin_W,
    const float* __restrict__ lin_b)
{
    __shared__ float s_h[544];   // padded h: idx(k) = k + 2*(k>>5)
    __shared__ float s_red[8];   // projection partials

    const int b    = blockIdx.x;
    const int tid  = threadIdx.x;
    const int wid  = tid >> 5;               // warps 0..3 = hidden units + pollers
    const int lane = tid & 31;
    const int gate = lane >> 3;              // 0..3 = i,f,g,o
    const int q    = lane & 7;               // 64-wide k-partition
    const int rep  = b & 3;                  // replica this CTA reads

    // compute warps (wid<4): persistent Whh rows as packed f32x2
    unsigned long long we2[32], wd2[32];
    if (wid < 4) {
        const int grow = gate * H_DIM + b * 4 + wid;
        const float2* se = (const float2*)(enc_Whh + (size_t)grow * H_DIM + 64 * q);
        const float2* sd = (const float2*)(dec_Whh + (size_t)grow * H_DIM + 64 * q);
#pragma unroll
        for (int t = 0; t < 32; t++) { float2 v = se[t]; we2[t] = pack2(v.x, v.y); }
#pragma unroll
        for (int t = 0; t < 32; t++) { float2 v = sd[t]; wd2[t] = pack2(v.x, v.y); }
    }
    // projection weights: thread covers h[2*tid], h[2*tid+1] of out dim d = b
    const float lw0 = __ldg(lin_W + b * H_DIM + 2 * tid);
    const float lw1 = __ldg(lin_W + b * H_DIM + 2 * tid + 1);
    const float lb  = __ldg(lin_b + b);

    float c_reg = 0.f;
    unsigned bar = 0;            // completed steps
    int buf = 0;                 // parity holding current h
    float4 pre_next = (wid < 4)
        ? __ldg((const float4*)(pre_row(0) + (b << 4) + (wid << 2)))
        : make_float4(0.f, 0.f, 0.f, 0.f);
    __syncthreads();

    // read 512-wide h (parity buf, replica b&3) into padded SMEM
    auto stage = [&]() {
        if (tid < NCTA) {
            const float4 hv = __ldcg((const float4*)&g_hp[buf][rep][tid][0]);
            const int base = 4 * tid + 2 * (tid >> 3);
            s_h[base + 0] = hv.x;
            s_h[base + 1] = hv.y;
            s_h[base + 2] = hv.z;
            s_h[base + 3] = hv.w;
        }
        __syncthreads();
    };

    auto step = [&](const unsigned long long (&w2)[32], unsigned u) {
        const float4 pcur = pre_next;
        if (wid < 4)
            pre_next = __ldg((const float4*)(pre_row(u + 1) + (b << 4) + (wid << 2)));
        stage();
        if (wid < 4) {
            const unsigned long long* h_lo = (const unsigned long long*)(s_h + 68 * q);
            const unsigned long long* h_hi = (const unsigned long long*)(s_h + 68 * q + 34);
            unsigned long long a0 = 0ull, a1 = 0ull, a2 = 0ull, a3 = 0ull;
#pragma unroll
            for (int t = 0; t < 16; t += 4) {
                a0 = fma2(w2[t + 0], h_lo[t + 0], a0);
                a1 = fma2(w2[t + 1], h_lo[t + 1], a1);
                a2 = fma2(w2[t + 2], h_lo[t + 2], a2);
                a3 = fma2(w2[t + 3], h_lo[t + 3], a3);
            }
#pragma unroll
            for (int t = 0; t < 16; t += 4) {
                a0 = fma2(w2[16 + t + 0], h_hi[t + 0], a0);
                a1 = fma2(w2[16 + t + 1], h_hi[t + 1], a1);
                a2 = fma2(w2[16 + t + 2], h_hi[t + 2], a2);
                a3 = fma2(w2[16 + t + 3], h_hi[t + 3], a3);
            }
            const unsigned long long at = add2(add2(a0, a1), add2(a2, a3));
            float sum = __uint_as_float((unsigned)at) + __uint_as_float((unsigned)(at >> 32));
            sum += __shfl_xor_sync(0xffffffffu, sum, 1);
            sum += __shfl_xor_sync(0xffffffffu, sum, 2);
            sum += __shfl_xor_sync(0xffffffffu, sum, 4);
            // distributed activations: lanes 0,8,16,24 activate their own gate
            float act = 0.f;
            if ((lane & 7) == 0) {
                const float pg = (gate == 0) ? pcur.x : (gate == 1) ? pcur.y
                               : (gate == 2) ? pcur.z : pcur.w;
                const float gs = sum + pg;
                act = (gate == 2) ? tanh_fast(gs) : sigm(gs);
            }
            const float ai = __shfl_sync(0xffffffffu, act, 0);
            const float af = __shfl_sync(0xffffffffu, act, 8);
            const float ag = __shfl_sync(0xffffffffu, act, 16);
            const float ao = __shfl_sync(0xffffffffu, act, 24);
            if (lane == 0) {
                const float cn = fmaf(af, c_reg, ai * ag);
                const float hn = ao * tanh_fast(cn);
                c_reg = cn;
#pragma unroll
                for (int r = 0; r < 4; r++) g_hp[buf ^ 1][r][b][wid] = hn;  // 4 replicas
            }
        }
        __syncthreads();   // all h stores done (bar.sync + release below = cumulativity)
        bar++;
        if (tid < 4) {
            // arrive: plain release STORE of step number (no RMW serialization)
            asm volatile("st.release.gpu.global.u32 [%0], %1;"
                         :: "l"(&g_flagU[tid][b]), "r"(bar) : "memory");
        }
        if (wid < 4) {
            // warp w polls flag line w of replica `rep` (32 flags, coalesced);
            // post-poll __syncthreads combines the 4 warps' verdicts.
            const unsigned int* fp = &g_flagU[rep][(wid << 5) | lane];
            unsigned v;
            do {
                asm volatile("ld.acquire.gpu.global.u32 %0, [%1];"
                             : "=r"(v) : "l"(fp) : "memory");
            } while (__any_sync(0xffffffffu, v < bar));
        }
        __syncthreads();
        buf ^= 1;
    };

    auto proj = [&](int i) {
        stage();
        const float2 hv = *(const float2*)(s_h + 2 * tid + 2 * (tid >> 4));
        float v = fmaf(lw0, hv.x, lw1 * hv.y);
#pragma unroll
        for (int m = 16; m >= 1; m >>= 1) v += __shfl_xor_sync(0xffffffffu, v, m);
        if (lane == 0) s_red[wid] = v;
        __syncthreads();   // also guards s_h reads vs next step's stage writes
        if (tid == 0) {
            float acc = lb;
#pragma unroll
            for (int t = 0; t < 8; t++) acc += s_red[t];
            g_outs[(NCOLS - 1 - i) * D_DIM + b] = acc;
        }
    };

    unsigned u = 0;
    // ---- encoder: 64 steps on batch row 255 only ----
    for (int t = 0; t < A_DIM; t++) step(we2, u++);
    // ---- decoder: 256 columns; projection first, then 64 steps (last column dead) ----
    for (int i = 0; i < NCOLS; i++) {
        proj(i);
        if (i < NCOLS - 1)
            for (int t = 0; t < A_DIM; t++) step(wd2, u++);
    }
}

// ---------------- broadcast outs (256x128) over leading A dim -> (64,256,128) ----------------
__global__ void bcast_kernel(float* __restrict__ out)
{
    const unsigned idx = blockIdx.x * blockDim.x + threadIdx.x;
    out[idx] = g_outs[idx & (NCOLS * D_DIM - 1)];
}

// ---------------- launch ----------------
extern "C" void kernel_launch(void* const* d_in, const int* in_sizes, int n_in,
                              void* d_out, int out_size)
{
    const float* x       = (const float*)d_in[0];
    const float* enc_Wih = (const float*)d_in[1];
    const float* enc_Whh = (const float*)d_in[2];
    const float* enc_bih = (const float*)d_in[3];
    const float* enc_bhh = (const float*)d_in[4];
    const float* dec_Wih = (const float*)d_in[5];
    const float* dec_Whh = (const float*)d_in[6];
    const float* dec_bih = (const float*)d_in[7];
    const float* dec_bhh = (const float*)d_in[8];
    const float* lin_W   = (const float*)d_in[9];
    const float* lin_b   = (const float*)d_in[10];
    float* out = (float*)d_out;

    // pre-activations (off the critical chain)
    pre_gemm_kernel<<<dim3(1, G4 / BN), TPB>>>(x, enc_Wih, enc_bih, enc_bhh, 0);
    pre_gemm_kernel<<<dim3((NCOLS * A_DIM) / BM, G4 / BN), TPB>>>(x, dec_Wih, dec_bih, dec_bhh, 1);

    // reset h lines + flags every launch (graph replays)
    init_kernel<<<128, 256>>>();

    // sequential recurrent chain: 16384 steps, persistent 128-CTA grid
    lstm_seq_kernel<<<NCTA, TPB>>>(enc_Whh, dec_Whh, lin_W, lin_b);

    // broadcast to (64, 256, 128)
    bcast_kernel<<<(64u * 256u * 128u) / 256u, 256u>>>(out);
}

// round 17
// speedup vs baseline: 2.3029x; 2.3029x over previous
#include <cuda_runtime.h>
#include <cstdint>
#include <cstddef>

#define A_DIM 64
#define B_DIM 256
#define D_DIM 128
#define H_DIM 512
#define G4    2048
#define NCTA  128
#define TPB   256
#define NCOLS 256

// ---------------- device scratch (static: no allocations allowed) ----------------
__device__ float g_pre_enc[A_DIM * G4];                       // transposed gate layout
__device__ float g_pre_dec[(size_t)NCOLS * A_DIM * G4];       // transposed gate layout
// h exchange: [parity][replica][cta] -> private 128B line, words 0..3 = h[4*cta .. 4*cta+3]
__device__ __align__(128) float g_hp[2][4][NCTA][32];
// barrier counters: 4 replicas x 16 groups (8 CTAs each), each on its own 128B line
__device__ __align__(128) unsigned int g_ctrB[4][16][32];
__device__ float g_outs[NCOLS * D_DIM];                       // per-column projections

// new gate column ng = cta*16 + wid*4 + gate  ->  old row = gate*512 + cta*4 + wid
__host__ __device__ __forceinline__ int inv_gate_map(int ng)
{
    const int gate = ng & 3;
    const int w    = (ng >> 2) & 3;
    const int cta  = ng >> 4;
    return gate * H_DIM + cta * 4 + w;
}

// ---------------- pre-activation GEMM (writes transposed gate layout) ----------------
#define BM 64
#define BN 64
#define BK 64

__global__ void pre_gemm_kernel(const float* __restrict__ x,
                                const float* __restrict__ Wih,
                                const float* __restrict__ bih,
                                const float* __restrict__ bhh,
                                int dec)
{
    __shared__ float Xs[BM][BK + 1];
    __shared__ float Ws[BN][BK + 1];
    float* __restrict__ outp = dec ? g_pre_dec : g_pre_enc;

    const int m0 = blockIdx.x * BM;
    const int n0 = blockIdx.y * BN;
    const int tid = threadIdx.x;
    const int tx = tid & 15;
    const int ty = tid >> 4;

    float acc[4][4];
#pragma unroll
    for (int r = 0; r < 4; r++)
#pragma unroll
        for (int c = 0; c < 4; c++) acc[r][c] = 0.f;

    const int lr = tid >> 2;
    const int lc = (tid & 3) * 16;

#pragma unroll
    for (int kit = 0; kit < 2; kit++) {
        const int k0 = kit * BK;
        {
            const int m = m0 + lr;
            const float* src;
            if (dec) {
                const int i = m >> 6;
                const int t = m & 63;
                src = x + ((size_t)(t * B_DIM + (B_DIM - 1 - i))) * D_DIM + k0 + lc;
            } else {
                src = x + ((size_t)(m * B_DIM + (B_DIM - 1))) * D_DIM + k0 + lc;
            }
#pragma unroll
            for (int q = 0; q < 4; q++) {
                float4 v = *(const float4*)(src + q * 4);
                Xs[lr][lc + q * 4 + 0] = v.x;
                Xs[lr][lc + q * 4 + 1] = v.y;
                Xs[lr][lc + q * 4 + 2] = v.z;
                Xs[lr][lc + q * 4 + 3] = v.w;
            }
        }
        {
            const int og = inv_gate_map(n0 + lr);
            const float* src = Wih + (size_t)og * D_DIM + k0 + lc;
#pragma unroll
            for (int q = 0; q < 4; q++) {
                float4 v = *(const float4*)(src + q * 4);
                Ws[lr][lc + q * 4 + 0] = v.x;
                Ws[lr][lc + q * 4 + 1] = v.y;
                Ws[lr][lc + q * 4 + 2] = v.z;
                Ws[lr][lc + q * 4 + 3] = v.w;
            }
        }
        __syncthreads();
#pragma unroll 16
        for (int kk = 0; kk < BK; kk++) {
            float a[4], bb[4];
#pragma unroll
            for (int r = 0; r < 4; r++) a[r] = Xs[ty * 4 + r][kk];
#pragma unroll
            for (int c = 0; c < 4; c++) bb[c] = Ws[tx * 4 + c][kk];
#pragma unroll
            for (int r = 0; r < 4; r++)
#pragma unroll
                for (int c = 0; c < 4; c++) acc[r][c] = fmaf(a[r], bb[c], acc[r][c]);
        }
        __syncthreads();
    }
#pragma unroll
    for (int r = 0; r < 4; r++) {
        const int m = m0 + ty * 4 + r;
#pragma unroll
        for (int c = 0; c < 4; c++) {
            const int ng = n0 + tx * 4 + c;
            const int og = inv_gate_map(ng);
            outp[(size_t)m * G4 + ng] = acc[r][c] + bih[og] + bhh[og];
        }
    }
}

// ---------------- init (runs every launch) ----------------
__global__ void init_kernel()
{
    const int t = blockIdx.x * blockDim.x + threadIdx.x;
    if (t < 2 * 4 * NCTA * 32) ((float*)g_hp)[t] = 0.f;
    if (t < 4 * 16 * 32) ((unsigned int*)g_ctrB)[t] = 0u;
}

// ---------------- fast math helpers ----------------
__device__ __forceinline__ float tanh_fast(float x)
{
    float y;
    asm("tanh.approx.f32 %0, %1;" : "=f"(y) : "f"(x));
    return y;
}
__device__ __forceinline__ float sigm(float x)
{
    return fmaf(tanh_fast(0.5f * x), 0.5f, 0.5f);
}
__device__ __forceinline__ unsigned long long fma2(unsigned long long a,
                                                   unsigned long long b,
                                                   unsigned long long c)
{
    unsigned long long d;
    asm("fma.rn.f32x2 %0, %1, %2, %3;" : "=l"(d) : "l"(a), "l"(b), "l"(c));
    return d;
}
__device__ __forceinline__ unsigned long long add2(unsigned long long a,
                                                   unsigned long long b)
{
    unsigned long long d;
    asm("add.rn.f32x2 %0, %1, %2;" : "=l"(d) : "l"(a), "l"(b));
    return d;
}
__device__ __forceinline__ unsigned long long pack2(float lo, float hi)
{
    return ((unsigned long long)__float_as_uint(hi) << 32) | (unsigned long long)__float_as_uint(lo);
}
__device__ __forceinline__ const float* pre_row(unsigned u)
{
    return (u < A_DIM) ? (g_pre_enc + (size_t)u * G4)
                       : (g_pre_dec + (size_t)(u - A_DIM) * G4);
}

// ---------------- sequential recurrent kernel ----------------
__global__ void __launch_bounds__(TPB, 1) lstm_seq_kernel(
    const float* __restrict__ enc_Whh,
    const float* __restrict__ dec_Whh,
    const float* __restrict__ lin_W,
    const float* __restrict__ lin_b)
{
    __shared__ float s_h[544];   // padded h: idx(k) = k + 2*(k>>5)
    __shared__ float s_red[8];   // projection partials

    const int b    = blockIdx.x;
    const int tid  = threadIdx.x;
    const int wid  = tid >> 5;               // warps 0..3 = hidden units + stagers
    const int lane = tid & 31;
    const int gate = lane >> 3;              // 0..3 = i,f,g,o
    const int q    = lane & 7;               // 64-wide k-partition
    const int rep  = b & 3;                  // replica this CTA reads
    const int grp  = b >> 3;                 // counter group (8 CTAs each)

    // compute warps (wid<4): persistent Whh rows as packed f32x2
    unsigned long long we2[32], wd2[32];
    if (wid < 4) {
        const int grow = gate * H_DIM + b * 4 + wid;
        const float2* se = (const float2*)(enc_Whh + (size_t)grow * H_DIM + 64 * q);
        const float2* sd = (const float2*)(dec_Whh + (size_t)grow * H_DIM + 64 * q);
#pragma unroll
        for (int t = 0; t < 32; t++) { float2 v = se[t]; we2[t] = pack2(v.x, v.y); }
#pragma unroll
        for (int t = 0; t < 32; t++) { float2 v = sd[t]; wd2[t] = pack2(v.x, v.y); }
    }
    // projection weights: thread covers h[2*tid], h[2*tid+1] of out dim d = b
    const float lw0 = __ldg(lin_W + b * H_DIM + 2 * tid);
    const float lw1 = __ldg(lin_W + b * H_DIM + 2 * tid + 1);
    const float lb  = __ldg(lin_b + b);

    float c_reg = 0.f;
    unsigned bar = 0;            // completed steps
    int buf = 0;                 // parity holding current h
    float4 pre_next = (wid < 4)
        ? __ldg((const float4*)(pre_row(0) + (b << 4) + (wid << 2)))
        : make_float4(0.f, 0.f, 0.f, 0.f);
    __syncthreads();

    // read 512-wide h (parity buf, replica b&3) into padded SMEM
    auto stage = [&]() {
        if (tid < NCTA) {
            const float4 hv = __ldcg((const float4*)&g_hp[buf][rep][tid][0]);
            const int base = 4 * tid + 2 * (tid >> 3);
            s_h[base + 0] = hv.x;
            s_h[base + 1] = hv.y;
            s_h[base + 2] = hv.z;
            s_h[base + 3] = hv.w;
        }
        __syncthreads();
    };

    auto step = [&](const unsigned long long (&w2)[32], unsigned u) {
        const float4 pcur = pre_next;
        if (wid < 4)
            pre_next = __ldg((const float4*)(pre_row(u + 1) + (b << 4) + (wid << 2)));
        stage();
        if (wid < 4) {
            const unsigned long long* h_lo = (const unsigned long long*)(s_h + 68 * q);
            const unsigned long long* h_hi = (const unsigned long long*)(s_h + 68 * q + 34);
            unsigned long long a0 = 0ull, a1 = 0ull, a2 = 0ull, a3 = 0ull;
#pragma unroll
            for (int t = 0; t < 16; t += 4) {
                a0 = fma2(w2[t + 0], h_lo[t + 0], a0);
                a1 = fma2(w2[t + 1], h_lo[t + 1], a1);
                a2 = fma2(w2[t + 2], h_lo[t + 2], a2);
                a3 = fma2(w2[t + 3], h_lo[t + 3], a3);
            }
#pragma unroll
            for (int t = 0; t < 16; t += 4) {
                a0 = fma2(w2[16 + t + 0], h_hi[t + 0], a0);
                a1 = fma2(w2[16 + t + 1], h_hi[t + 1], a1);
                a2 = fma2(w2[16 + t + 2], h_hi[t + 2], a2);
                a3 = fma2(w2[16 + t + 3], h_hi[t + 3], a3);
            }
            const unsigned long long at = add2(add2(a0, a1), add2(a2, a3));
            float sum = __uint_as_float((unsigned)at) + __uint_as_float((unsigned)(at >> 32));
            sum += __shfl_xor_sync(0xffffffffu, sum, 1);
            sum += __shfl_xor_sync(0xffffffffu, sum, 2);
            sum += __shfl_xor_sync(0xffffffffu, sum, 4);
            // distributed activations: lanes 0,8,16,24 activate their own gate
            float act = 0.f;
            if ((lane & 7) == 0) {
                const float pg = (gate == 0) ? pcur.x : (gate == 1) ? pcur.y
                               : (gate == 2) ? pcur.z : pcur.w;
                const float gs = sum + pg;
                act = (gate == 2) ? tanh_fast(gs) : sigm(gs);
            }
            const float ai = __shfl_sync(0xffffffffu, act, 0);
            const float af = __shfl_sync(0xffffffffu, act, 8);
            const float ag = __shfl_sync(0xffffffffu, act, 16);
            const float ao = __shfl_sync(0xffffffffu, act, 24);
            if (lane == 0) {
                const float cn = fmaf(af, c_reg, ai * ag);
                const float hn = ao * tanh_fast(cn);
                c_reg = cn;
#pragma unroll
                for (int r = 0; r < 4; r++) g_hp[buf ^ 1][r][b][wid] = hn;  // 4 replicas
            }
        }
        __syncthreads();   // all h stores done before the release-arrives below
        bar++;
        if (tid < 4) {
            // arrive on all 4 replicas of this CTA's group counter (distinct lines,
            // parallel; 8 RMWs serialize per line instead of 16)
            asm volatile("red.release.gpu.global.add.u32 [%0], 1;"
                         :: "l"(&g_ctrB[tid][grp][0]) : "memory");
        }
        if (tid < 16) {
            // 16 lanes of warp 0 observe the 16 group counters (replica b&3):
            // 32 spinner-lanes per line chip-wide
            const unsigned tgt = bar * 8u;
            const unsigned int* cp = &g_ctrB[rep][tid][0];
            unsigned v;
            do {
                asm volatile("ld.acquire.gpu.global.u32 %0, [%1];"
                             : "=r"(v) : "l"(cp) : "memory");
            } while (v < tgt);
        }
        __syncthreads();
        buf ^= 1;
    };

    auto proj = [&](int i) {
        stage();
        const float2 hv = *(const float2*)(s_h + 2 * tid + 2 * (tid >> 4));
        float v = fmaf(lw0, hv.x, lw1 * hv.y);
#pragma unroll
        for (int m = 16; m >= 1; m >>= 1) v += __shfl_xor_sync(0xffffffffu, v, m);
        if (lane == 0) s_red[wid] = v;
        __syncthreads();   // also guards s_h reads vs next step's stage writes
        if (tid == 0) {
            float acc = lb;
#pragma unroll
            for (int t = 0; t < 8; t++) acc += s_red[t];
            g_outs[(NCOLS - 1 - i) * D_DIM + b] = acc;
        }
    };

    unsigned u = 0;
    // ---- encoder: 64 steps on batch row 255 only ----
    for (int t = 0; t < A_DIM; t++) step(we2, u++);
    // ---- decoder: 256 columns; projection first, then 64 steps (last column dead) ----
    for (int i = 0; i < NCOLS; i++) {
        proj(i);
        if (i < NCOLS - 1)
            for (int t = 0; t < A_DIM; t++) step(wd2, u++);
    }
}

// ---------------- broadcast outs (256x128) over leading A dim -> (64,256,128) ----------------
__global__ void bcast_kernel(float* __restrict__ out)
{
    const unsigned idx = blockIdx.x * blockDim.x + threadIdx.x;
    out[idx] = g_outs[idx & (NCOLS * D_DIM - 1)];
}

// ---------------- launch ----------------
extern "C" void kernel_launch(void* const* d_in, const int* in_sizes, int n_in,
                              void* d_out, int out_size)
{
    const float* x       = (const float*)d_in[0];
    const float* enc_Wih = (const float*)d_in[1];
    const float* enc_Whh = (const float*)d_in[2];
    const float* enc_bih = (const float*)d_in[3];
    const float* enc_bhh = (const float*)d_in[4];
    const float* dec_Wih = (const float*)d_in[5];
    const float* dec_Whh = (const float*)d_in[6];
    const float* dec_bih = (const float*)d_in[7];
    const float* dec_bhh = (const float*)d_in[8];
    const float* lin_W   = (const float*)d_in[9];
    const float* lin_b   = (const float*)d_in[10];
    float* out = (float*)d_out;

    // pre-activations (off the critical chain)
    pre_gemm_kernel<<<dim3(1, G4 / BN), TPB>>>(x, enc_Wih, enc_bih, enc_bhh, 0);
    pre_gemm_kernel<<<dim3((NCOLS * A_DIM) / BM, G4 / BN), TPB>>>(x, dec_Wih, dec_bih, dec_bhh, 1);

    // reset h lines + counters every launch (graph replays)
    init_kernel<<<128, 256>>>();

    // sequential recurrent chain: 16384 steps, persistent 128-CTA grid
    lstm_seq_kernel<<<NCTA, TPB>>>(enc_Whh, dec_Whh, lin_W, lin_b);

    // broadcast to (64, 256, 128)
    bcast_kernel<<<(64u * 256u * 128u) / 256u, 256u>>>(out);
}